// round 15
// baseline (speedup 1.0000x reference)
#include <cuda_runtime.h>
#include <cuda_bf16.h>
#include <cuda_fp16.h>
#include <cstdint>
#include <math.h>

// ---------------------------------------------------------------------------
// TelephoneAttentionND  (B=2, L=2048, C=1024, H=16, D=64, K=64, S=33)
// Stage 1: proj (warp/2-tokens) -> freq/phase/expo + x fp16 (g_xa)
// cvt    : w_kern + w_out -> fp16 (single launch)
// Stage 2: kern GEMM [fp16 mma, r9 config] (+bias, +fused sumsq) -> g_proj
// Stage 3+4: attn (16 tokens x 1 head / block), fp32 gathers from x,
//            2 samples/iter, no cvt in inner loop               -> g_ha
// Stage 5: out GEMM + silu                                      -> d_out
// ---------------------------------------------------------------------------

#define BATCH 2
#define SEQLEN 2048
#define CH 1024
#define NHEAD 16
#define HDIM 64
#define KSIZE 64
#define TOKENS (BATCH * SEQLEN)   // 4096

// scratch (device globals; no allocation allowed)
__device__ float g_freq[TOKENS * NHEAD];
__device__ float g_phase[TOKENS * NHEAD];
__device__ float g_expo[TOKENS];
__device__ float g_sumsq[TOKENS];
__device__ float g_proj[(size_t)TOKENS * CH];   // gemm1 out (fp32)
__device__ __half g_xa[(size_t)TOKENS * CH];    // x in fp16 (GEMM1 A operand)
__device__ __half g_ha[(size_t)TOKENS * CH];    // hidden in fp16
__device__ __half g_wk[(size_t)CH * CH];        // w_kern fp16
__device__ __half g_wo[(size_t)CH * CH];        // w_out fp16

__device__ __forceinline__ float siluf(float v) {
    return v / (1.0f + expf(-v));
}

__device__ __forceinline__ void mma_f16_16x8x16(
    float c[4], const uint32_t a[4], uint32_t b0, uint32_t b1)
{
    asm volatile(
        "mma.sync.aligned.m16n8k16.row.col.f32.f16.f16.f32 "
        "{%0, %1, %2, %3}, {%4, %5, %6, %7}, {%8, %9}, {%0, %1, %2, %3};"
        : "+f"(c[0]), "+f"(c[1]), "+f"(c[2]), "+f"(c[3])
        : "r"(a[0]), "r"(a[1]), "r"(a[2]), "r"(a[3]), "r"(b0), "r"(b1));
}

__device__ __forceinline__ void ldsm_x4(uint32_t r[4], uint32_t addr) {
    asm volatile(
        "ldmatrix.sync.aligned.m8n8.x4.shared.b16 {%0, %1, %2, %3}, [%4];"
        : "=r"(r[0]), "=r"(r[1]), "=r"(r[2]), "=r"(r[3]) : "r"(addr));
}

__device__ __forceinline__ uint32_t smem_u32(const void* p) {
    uint32_t a;
    asm("{ .reg .u64 t; cvta.to.shared.u64 t, %1; cvt.u32.u64 %0, t; }"
        : "=r"(a) : "l"(p));
    return a;
}

__device__ __forceinline__ void cp_async16(uint32_t dst, const void* src) {
    asm volatile("cp.async.ca.shared.global [%0], [%1], 16;"
                 :: "r"(dst), "l"(src));
}
#define CP_COMMIT() asm volatile("cp.async.commit_group;" ::: "memory")
#define CP_WAIT2()  asm volatile("cp.async.wait_group 2;" ::: "memory")

// ===========================================================================
// cvt: both weight matrices fp32 -> fp16 in ONE launch.
// ===========================================================================
__global__ __launch_bounds__(256) void cvt_w_kernel(
    const float* __restrict__ wk, __half* __restrict__ ok,
    const float* __restrict__ wo, __half* __restrict__ oo, int n4each)
{
    int idx = blockIdx.x * 256 + threadIdx.x;
    const float* in;
    __half* out;
    if (idx < n4each) {
        in = wk; out = ok;
    } else {
        in = wo; out = oo; idx -= n4each;
    }
    const float4 v = ((const float4*)in)[idx];
    __half2 h0 = __floats2half2_rn(v.x, v.y);
    __half2 h1 = __floats2half2_rn(v.z, v.w);
    uint2 o;
    o.x = *(uint32_t*)&h0;
    o.y = *(uint32_t*)&h1;
    ((uint2*)out)[idx] = o;
}

// ===========================================================================
// Stage 1: wave+exp projection, warp-per-2-tokens, no inner syncs (r13 form).
// Side effects: writes x as fp16 to g_xa; zeroes g_sumsq for its tokens.
// ===========================================================================
__global__ __launch_bounds__(256) void proj_small_kernel(
    const float* __restrict__ x,
    const float* __restrict__ w_wave, const float* __restrict__ b_wave,
    const float* __restrict__ g_wave,
    const float* __restrict__ w_exp, const float* __restrict__ b_exp,
    const float* __restrict__ g_exp)
{
    const int tid  = threadIdx.x;
    const int wid  = tid >> 5;
    const int lane = tid & 31;
    const int tok0 = blockIdx.x * 16 + wid * 2;

    __shared__ float po[16][34];

    if (tid < 16) g_sumsq[blockIdx.x * 16 + tid] = 0.0f;

    float4 xr0[8], xr1[8];
    {
        const float* x0 = x + (size_t)tok0 * CH;
        const float* x1 = x0 + CH;
        uint2* xa0 = (uint2*)(g_xa + (size_t)tok0 * CH);
        uint2* xa1 = (uint2*)(g_xa + (size_t)(tok0 + 1) * CH);
        #pragma unroll
        for (int j = 0; j < 8; j++) {
            xr0[j] = *(const float4*)(x0 + j * 128 + lane * 4);
            xr1[j] = *(const float4*)(x1 + j * 128 + lane * 4);
            __half2 a0 = __floats2half2_rn(xr0[j].x, xr0[j].y);
            __half2 a1 = __floats2half2_rn(xr0[j].z, xr0[j].w);
            __half2 b0 = __floats2half2_rn(xr1[j].x, xr1[j].y);
            __half2 b1 = __floats2half2_rn(xr1[j].z, xr1[j].w);
            uint2 pa, pb;
            pa.x = *(uint32_t*)&a0; pa.y = *(uint32_t*)&a1;
            pb.x = *(uint32_t*)&b0; pb.y = *(uint32_t*)&b1;
            xa0[j * 32 + lane] = pa;
            xa1[j * 32 + lane] = pb;
        }
    }

    for (int o = 0; o < 33; o++) {
        const float* wrow = (o < 32) ? (w_wave + (size_t)o * CH) : w_exp;
        float d0 = 0.f, d1 = 0.f;
        #pragma unroll
        for (int j = 0; j < 8; j++) {
            const float4 w4 = *(const float4*)(wrow + j * 128 + lane * 4);
            d0 += xr0[j].x * w4.x + xr0[j].y * w4.y
                + xr0[j].z * w4.z + xr0[j].w * w4.w;
            d1 += xr1[j].x * w4.x + xr1[j].y * w4.y
                + xr1[j].z * w4.z + xr1[j].w * w4.w;
        }
        #pragma unroll
        for (int d = 16; d > 0; d >>= 1) {
            d0 += __shfl_xor_sync(0xffffffffu, d0, d);
            d1 += __shfl_xor_sync(0xffffffffu, d1, d);
        }
        if (lane == 0) {
            const float bv = (o < 32) ? b_wave[o] : b_exp[0];
            po[wid * 2][o]     = d0 + bv;
            po[wid * 2 + 1][o] = d1 + bv;
        }
    }
    __syncthreads();

    #pragma unroll
    for (int it = 0; it < 2; it++) {
        const int tk = wid + it * 8;
        const int gtok = blockIdx.x * 16 + tk;
        float v = po[tk][lane];
        float sq = v * v;
        #pragma unroll
        for (int d = 16; d > 0; d >>= 1) sq += __shfl_xor_sync(0xffffffffu, sq, d);
        const float r = rsqrtf(sq * (1.0f / 32.0f) + 1e-6f);
        const float sil = siluf(g_wave[lane] * v * r);
        if (lane < 16) {
            g_freq[(size_t)gtok * NHEAD + lane] = 15.0f / (1.0f + expf(-sil)) + 1.0f;
        } else {
            g_phase[(size_t)gtok * NHEAD + (lane - 16)] = tanhf(sil) * 16.0f;
        }
        if (lane == 0) {
            const float ve = po[tk][32];
            const float y = g_exp[0] * ve * rsqrtf(ve * ve + 1e-6f);
            g_expo[gtok] = (1.0f / (1.0f + expf(-y))) * 3.5f + 0.5f;
        }
    }
}

// ===========================================================================
// Stages 2 & 5: fp16 mma m16n8k16 GEMM, ldmatrix, BK=32, cp.async 4-stage.
// 128x128 CTA tile, 128 threads = 4 warps (2x2), warp tile = 64x64.
// 2 CTAs/SM. (r9 configuration — FROZEN). Optional fused sumsq epilogue.
// ===========================================================================
#define GSTRIDE 20                                     // u32 per row
#define STG 4
#define STAGE_U32 (128 * GSTRIDE)                      // 2560 u32 per matrix stage
#define GEMM_SMEM (STG * STAGE_U32 * 2 * 4)            // 81920 bytes

template <bool BIAS, bool SILU, bool RMS>
__global__ __launch_bounds__(128, 2) void gemm_tc_kernel(
    const __half* __restrict__ A, const __half* __restrict__ B,
    const float* __restrict__ bias, float* __restrict__ C)
{
    extern __shared__ uint32_t smem32[];
    const uint32_t smem_base = smem_u32(smem32);
    const uint32_t BOFF = STG * STAGE_U32 * 4;   // byte offset of B region

    const int tid  = threadIdx.x;
    const int wid  = tid >> 5;
    const int lane = tid & 31;
    const int gid  = lane >> 2;     // groupID 0..7
    const int tig  = lane & 3;      // thread-in-group 0..3
    const int wm   = wid & 1;       // warp row (0..1) -> 64 rows each
    const int wn   = wid >> 1;      // warp col (0..1) -> 64 cols each

    const int bm = blockIdx.y * 128;
    const int bn = blockIdx.x * 128;

    const int r0 = tid >> 2;        // 0..31
    const int cc = tid & 3;
    const uint32_t sbase = smem_base + (uint32_t)(r0 * GSTRIDE + cc * 4) * 4;
    const __half* gA0 = A + (size_t)(bm + r0) * CH + cc * 8;
    const __half* gB0 = B + (size_t)(bn + r0) * CH + cc * 8;

    const int rA = (lane & 7) + ((lane >> 3) & 1) * 8;
    const int kA = (lane >> 4) * 4;                      // u32
    uint32_t a_addr[4];
    #pragma unroll
    for (int mt = 0; mt < 4; mt++) {
        const int row = wm * 64 + mt * 16 + rA;
        a_addr[mt] = smem_base + (uint32_t)(row * GSTRIDE + kA) * 4;
    }
    const int rB = (lane & 7) + ((lane >> 4) << 3);
    const int kB = ((lane >> 3) & 1) * 4;                // u32
    uint32_t b_addr[4];
    #pragma unroll
    for (int pr = 0; pr < 4; pr++) {
        const int row = wn * 64 + pr * 16 + rB;
        b_addr[pr] = smem_base + BOFF + (uint32_t)(row * GSTRIDE + kB) * 4;
    }

    float c[4][8][4];
    #pragma unroll
    for (int mt = 0; mt < 4; mt++)
        #pragma unroll
        for (int nt = 0; nt < 8; nt++)
            #pragma unroll
            for (int j = 0; j < 4; j++) c[mt][nt][j] = 0.0f;

    const int NCHUNK = CH / 32;   // 32

    #pragma unroll
    for (int s = 0; s < STG - 1; s++) {
        const uint32_t so = (uint32_t)(s * STAGE_U32) * 4;
        #pragma unroll
        for (int i = 0; i < 4; i++) {
            const uint32_t ro = (uint32_t)(i * 32 * GSTRIDE) * 4;
            cp_async16(sbase + so + ro, gA0 + (size_t)(i * 32) * CH + s * 32);
            cp_async16(sbase + so + ro + BOFF, gB0 + (size_t)(i * 32) * CH + s * 32);
        }
        CP_COMMIT();
    }

    for (int kc = 0; kc < NCHUNK; kc++) {
        CP_WAIT2();
        __syncthreads();

        if (kc + STG - 1 < NCHUNK) {
            const uint32_t so = (uint32_t)(((kc + STG - 1) & (STG - 1)) * STAGE_U32) * 4;
            const int k0 = (kc + STG - 1) * 32;
            #pragma unroll
            for (int i = 0; i < 4; i++) {
                const uint32_t ro = (uint32_t)(i * 32 * GSTRIDE) * 4;
                cp_async16(sbase + so + ro, gA0 + (size_t)(i * 32) * CH + k0);
                cp_async16(sbase + so + ro + BOFF, gB0 + (size_t)(i * 32) * CH + k0);
            }
        }
        CP_COMMIT();

        const uint32_t soff = (uint32_t)((kc & (STG - 1)) * STAGE_U32) * 4;

        #pragma unroll
        for (int ksub = 0; ksub < 2; ksub++) {
            const uint32_t ko = soff + ksub * 32;   // 8 u32 = 32B per ksub
            uint32_t a[4][4], b[4][4];
            #pragma unroll
            for (int mt = 0; mt < 4; mt++) ldsm_x4(a[mt], a_addr[mt] + ko);
            #pragma unroll
            for (int pr = 0; pr < 4; pr++) ldsm_x4(b[pr], b_addr[pr] + ko);
            #pragma unroll
            for (int mt = 0; mt < 4; mt++) {
                #pragma unroll
                for (int nt = 0; nt < 8; nt++)
                    mma_f16_16x8x16(c[mt][nt], a[mt],
                                    b[nt >> 1][(nt & 1) * 2],
                                    b[nt >> 1][(nt & 1) * 2 + 1]);
            }
        }
    }

    #pragma unroll
    for (int mt = 0; mt < 4; mt++) {
        const int row = bm + wm * 64 + mt * 16 + gid;
        float s0 = 0.f, s8 = 0.f;
        #pragma unroll
        for (int nt = 0; nt < 8; nt++) {
            const int col = bn + wn * 64 + nt * 8 + tig * 2;
            float u0 = c[mt][nt][0], u1 = c[mt][nt][1];
            float u2 = c[mt][nt][2], u3 = c[mt][nt][3];
            if (BIAS) {
                const float b0v = bias[col], b1v = bias[col + 1];
                u0 += b0v; u1 += b1v; u2 += b0v; u3 += b1v;
            }
            if (SILU) {
                u0 = siluf(u0); u1 = siluf(u1); u2 = siluf(u2); u3 = siluf(u3);
            }
            if (RMS) {
                s0 += u0 * u0 + u1 * u1;
                s8 += u2 * u2 + u3 * u3;
            }
            *(float2*)(C + (size_t)row * CH + col)       = make_float2(u0, u1);
            *(float2*)(C + (size_t)(row + 8) * CH + col) = make_float2(u2, u3);
        }
        if (RMS) {
            s0 += __shfl_xor_sync(0xffffffffu, s0, 1);
            s0 += __shfl_xor_sync(0xffffffffu, s0, 2);
            s8 += __shfl_xor_sync(0xffffffffu, s8, 1);
            s8 += __shfl_xor_sync(0xffffffffu, s8, 2);
            if (tig == 0) {
                atomicAdd(&g_sumsq[row], s0);
                atomicAdd(&g_sumsq[row + 8], s8);
            }
        }
    }
}

// ===========================================================================
// Stages 3+4: attention. Block = (16 consecutive tokens x ONE head),
// 512 threads = 16 warps, warp w -> token (tile*16 + w). Warp-local.
// Phase B: fp32 gathers directly from x (NO cvt in inner loop).
// 2 samples/iter: lane>>4 = sample parity, lane&15 = 4-channel group,
// 2 x LDG.128 per lane-iter. rinv from fused g_sumsq.
// ===========================================================================
__global__ __launch_bounds__(512) void attn_kernel(
    const float* __restrict__ x, const float* __restrict__ gk)
{
    const int h    = blockIdx.x & (NHEAD - 1);
    const int tile = blockIdx.x >> 4;
    const int tid  = threadIdx.x;
    const int w    = tid >> 5;
    const int lane = tid & 31;

    const int gt = tile * 16 + w;          // this warp's token
    const int b  = gt >> 11;
    const int l  = gt & (SEQLEN - 1);

    __shared__ float km[16][KSIZE];
    __shared__ float skf[16][34];
    __shared__ float skc[16][34];
    __shared__ int   sfl[16][34];

    // km for (token gt, head h): 64 channels, built warp-locally
    const float rinv = rsqrtf(g_sumsq[gt] * (1.0f / (float)CH) + 1e-6f);
    {
        const float2 pj = ((const float2*)(g_proj + (size_t)gt * CH + h * HDIM))[lane];
        const float2 gg = ((const float2*)(gk + h * HDIM))[lane];
        km[w][lane * 2]     = siluf(gg.x * pj.x * rinv);
        km[w][lane * 2 + 1] = siluf(gg.y * pj.y * rinv);
    }
    __syncwarp();

    const float f = g_freq[(size_t)gt * NHEAD + h];
    const float p = g_phase[(size_t)gt * NHEAD + h];
    const float e = g_expo[gt];

    // Phase A: per-sample scalars (lane-parallel), slot 33 zero-padded
    for (int s = lane; s < 34; s += 32) {
        if (s >= 33) {
            skf[w][s] = 0.0f; skc[w][s] = 0.0f; sfl[w][s] = 0;
        } else {
            const float off = (float)(s - 16);
            const float rel = off * f;
            const float pos = (float)l + rel + p;
            const float validf = (pos >= 0.0f && pos < (float)SEQLEN) ? 1.0f : 0.0f;
            const float pc = fminf(fmaxf(pos, 0.0f), (float)SEQLEN - 1.001f);
            const int   fl = (int)floorf(pc);
            const float frac = pc - (float)fl;
            const float ar = fabsf(rel);
            const float powr = expf(-e * log1pf(ar * (1.0f / (float)SEQLEN)));
            const float idxf = fminf(ar * (1.0f / 256.0f), 1.0f) * 63.0f;
            int i0 = (int)idxf; if (i0 > 62) i0 = 62;
            const float wc = idxf - (float)i0;
            const float kern =
                (km[w][i0] * (1.0f - wc) + km[w][i0 + 1] * wc) * powr * validf;
            skf[w][s] = kern * (1.0f - frac);
            skc[w][s] = kern * frac;
            sfl[w][s] = fl * (CH / 4);     // float4 row index
        }
    }
    __syncwarp();

    // Phase B: 2 samples/iter, fp32 float4 gathers, no conversions.
    const int sh = lane >> 4;              // sample parity
    const int c4 = lane & 15;              // 4-channel group
    const float4* xb = (const float4*)(x + ((size_t)b * SEQLEN) * CH + h * HDIM);
    float a0 = 0.f, a1 = 0.f, a2 = 0.f, a3 = 0.f;
    #pragma unroll 17
    for (int sp = 0; sp < 17; sp++) {
        const int s  = sp * 2 + sh;
        const float kf = skf[w][s];
        const float kc = skc[w][s];
        const int   o  = sfl[w][s] + c4;
        const float4 vf = xb[o];
        const float4 vc = xb[o + CH / 4];
        a0 += kf * vf.x + kc * vc.x;
        a1 += kf * vf.y + kc * vc.y;
        a2 += kf * vf.z + kc * vc.z;
        a3 += kf * vf.w + kc * vc.w;
    }
    // combine the two sample-parities
    a0 += __shfl_xor_sync(0xffffffffu, a0, 16);
    a1 += __shfl_xor_sync(0xffffffffu, a1, 16);
    a2 += __shfl_xor_sync(0xffffffffu, a2, 16);
    a3 += __shfl_xor_sync(0xffffffffu, a3, 16);

    if (lane < 16) {
        __half2 h0 = __floats2half2_rn(a0, a1);
        __half2 h1 = __floats2half2_rn(a2, a3);
        uint2 pk;
        pk.x = *(uint32_t*)&h0;
        pk.y = *(uint32_t*)&h1;
        ((uint2*)(g_ha + (size_t)gt * CH + h * HDIM))[c4] = pk;
    }
}

// ===========================================================================
// launch
// ===========================================================================
extern "C" void kernel_launch(void* const* d_in, const int* in_sizes, int n_in,
                              void* d_out, int out_size)
{
    const float* x      = (const float*)d_in[0];
    const float* w_wave = (const float*)d_in[1];
    const float* b_wave = (const float*)d_in[2];
    const float* g_wave = (const float*)d_in[3];
    const float* w_kern = (const float*)d_in[4];
    const float* b_kern = (const float*)d_in[5];
    const float* g_kern = (const float*)d_in[6];
    const float* w_exp  = (const float*)d_in[7];
    const float* b_exp  = (const float*)d_in[8];
    const float* g_exp  = (const float*)d_in[9];
    const float* w_out  = (const float*)d_in[10];
    float* out = (float*)d_out;

    float *proj_ptr;
    __half *xa_ptr, *ha_ptr, *wk_ptr, *wo_ptr;
    cudaGetSymbolAddress((void**)&proj_ptr, g_proj);
    cudaGetSymbolAddress((void**)&xa_ptr, g_xa);
    cudaGetSymbolAddress((void**)&ha_ptr, g_ha);
    cudaGetSymbolAddress((void**)&wk_ptr, g_wk);
    cudaGetSymbolAddress((void**)&wo_ptr, g_wo);

    cudaFuncSetAttribute(gemm_tc_kernel<true, false, true>,
                         cudaFuncAttributeMaxDynamicSharedMemorySize, GEMM_SMEM);
    cudaFuncSetAttribute(gemm_tc_kernel<false, true, false>,
                         cudaFuncAttributeMaxDynamicSharedMemorySize, GEMM_SMEM);

    // Stage 1: wave + exp projections (fp32) + x -> fp16 + zero g_sumsq
    proj_small_kernel<<<TOKENS / 16, 256>>>(x, w_wave, b_wave, g_wave,
                                            w_exp, b_exp, g_exp);

    // convert both weight matrices to fp16 (single launch)
    cvt_w_kernel<<<2 * (CH * CH / 4) / 256, 256>>>(w_kern, wk_ptr,
                                                   w_out, wo_ptr,
                                                   CH * CH / 4);

    // Stage 2: kern projection GEMM (+bias, +fused sumsq) via fp16 mma
    dim3 ggrid(CH / 128, TOKENS / 128);   // (8, 32) = 256 CTAs
    gemm_tc_kernel<true, false, true><<<ggrid, 128, GEMM_SMEM>>>(
        xa_ptr, wk_ptr, b_kern, proj_ptr);

    // Stages 3+4: attention (16 tokens x 1 head / block), fp32 gathers
    attn_kernel<<<TOKENS / 16 * NHEAD, 512>>>(x, g_kern);

    // Stage 5: output GEMM + silu via fp16 mma
    gemm_tc_kernel<false, true, false><<<ggrid, 128, GEMM_SMEM>>>(
        ha_ptr, wo_ptr, nullptr, out);
}

// round 16
// speedup vs baseline: 1.0290x; 1.0290x over previous
#include <cuda_runtime.h>
#include <cuda_bf16.h>
#include <cuda_fp16.h>
#include <cstdint>
#include <math.h>

// ---------------------------------------------------------------------------
// TelephoneAttentionND  (B=2, L=2048, C=1024, H=16, D=64, K=64, S=33)
// Stage 1: proj (warp/2-tokens) -> freq/phase/expo + x fp16 (g_xa)
// cvt    : w_kern + w_out -> fp16 (single launch)
// Stage 2: kern GEMM [fp16 mma, r9 config] (+bias)               -> g_proj
// rms_reduce: per-token rinv                                     -> g_rinv
// Stage 3+4: attn (16 tokens x 1 head / block), fp16 gathers,
//            2 samples/iter, float4-packed per-sample scalars    -> g_ha
// Stage 5: out GEMM + silu                                       -> d_out
// ---------------------------------------------------------------------------

#define BATCH 2
#define SEQLEN 2048
#define CH 1024
#define NHEAD 16
#define HDIM 64
#define KSIZE 64
#define TOKENS (BATCH * SEQLEN)   // 4096

// scratch (device globals; no allocation allowed)
__device__ float g_freq[TOKENS * NHEAD];
__device__ float g_phase[TOKENS * NHEAD];
__device__ float g_expo[TOKENS];
__device__ float g_rinv[TOKENS];
__device__ float g_proj[(size_t)TOKENS * CH];   // gemm1 out (fp32)
__device__ __half g_xa[(size_t)TOKENS * CH];    // x in fp16
__device__ __half g_ha[(size_t)TOKENS * CH];    // hidden in fp16
__device__ __half g_wk[(size_t)CH * CH];        // w_kern fp16
__device__ __half g_wo[(size_t)CH * CH];        // w_out fp16

__device__ __forceinline__ float siluf(float v) {
    return v / (1.0f + expf(-v));
}

__device__ __forceinline__ void mma_f16_16x8x16(
    float c[4], const uint32_t a[4], uint32_t b0, uint32_t b1)
{
    asm volatile(
        "mma.sync.aligned.m16n8k16.row.col.f32.f16.f16.f32 "
        "{%0, %1, %2, %3}, {%4, %5, %6, %7}, {%8, %9}, {%0, %1, %2, %3};"
        : "+f"(c[0]), "+f"(c[1]), "+f"(c[2]), "+f"(c[3])
        : "r"(a[0]), "r"(a[1]), "r"(a[2]), "r"(a[3]), "r"(b0), "r"(b1));
}

__device__ __forceinline__ void ldsm_x4(uint32_t r[4], uint32_t addr) {
    asm volatile(
        "ldmatrix.sync.aligned.m8n8.x4.shared.b16 {%0, %1, %2, %3}, [%4];"
        : "=r"(r[0]), "=r"(r[1]), "=r"(r[2]), "=r"(r[3]) : "r"(addr));
}

__device__ __forceinline__ uint32_t smem_u32(const void* p) {
    uint32_t a;
    asm("{ .reg .u64 t; cvta.to.shared.u64 t, %1; cvt.u32.u64 %0, t; }"
        : "=r"(a) : "l"(p));
    return a;
}

__device__ __forceinline__ void cp_async16(uint32_t dst, const void* src) {
    asm volatile("cp.async.ca.shared.global [%0], [%1], 16;"
                 :: "r"(dst), "l"(src));
}
#define CP_COMMIT() asm volatile("cp.async.commit_group;" ::: "memory")
#define CP_WAIT2()  asm volatile("cp.async.wait_group 2;" ::: "memory")

// ===========================================================================
// cvt: both weight matrices fp32 -> fp16 in ONE launch.
// ===========================================================================
__global__ __launch_bounds__(256) void cvt_w_kernel(
    const float* __restrict__ wk, __half* __restrict__ ok,
    const float* __restrict__ wo, __half* __restrict__ oo, int n4each)
{
    int idx = blockIdx.x * 256 + threadIdx.x;
    const float* in;
    __half* out;
    if (idx < n4each) {
        in = wk; out = ok;
    } else {
        in = wo; out = oo; idx -= n4each;
    }
    const float4 v = ((const float4*)in)[idx];
    __half2 h0 = __floats2half2_rn(v.x, v.y);
    __half2 h1 = __floats2half2_rn(v.z, v.w);
    uint2 o;
    o.x = *(uint32_t*)&h0;
    o.y = *(uint32_t*)&h1;
    ((uint2*)out)[idx] = o;
}

// ===========================================================================
// Stage 1: wave+exp projection, warp-per-2-tokens, no inner syncs.
// Side effect: writes x as fp16 to g_xa.
// ===========================================================================
__global__ __launch_bounds__(256) void proj_small_kernel(
    const float* __restrict__ x,
    const float* __restrict__ w_wave, const float* __restrict__ b_wave,
    const float* __restrict__ g_wave,
    const float* __restrict__ w_exp, const float* __restrict__ b_exp,
    const float* __restrict__ g_exp)
{
    const int tid  = threadIdx.x;
    const int wid  = tid >> 5;
    const int lane = tid & 31;
    const int tok0 = blockIdx.x * 16 + wid * 2;

    __shared__ float po[16][34];

    float4 xr0[8], xr1[8];
    {
        const float* x0 = x + (size_t)tok0 * CH;
        const float* x1 = x0 + CH;
        uint2* xa0 = (uint2*)(g_xa + (size_t)tok0 * CH);
        uint2* xa1 = (uint2*)(g_xa + (size_t)(tok0 + 1) * CH);
        #pragma unroll
        for (int j = 0; j < 8; j++) {
            xr0[j] = *(const float4*)(x0 + j * 128 + lane * 4);
            xr1[j] = *(const float4*)(x1 + j * 128 + lane * 4);
            __half2 a0 = __floats2half2_rn(xr0[j].x, xr0[j].y);
            __half2 a1 = __floats2half2_rn(xr0[j].z, xr0[j].w);
            __half2 b0 = __floats2half2_rn(xr1[j].x, xr1[j].y);
            __half2 b1 = __floats2half2_rn(xr1[j].z, xr1[j].w);
            uint2 pa, pb;
            pa.x = *(uint32_t*)&a0; pa.y = *(uint32_t*)&a1;
            pb.x = *(uint32_t*)&b0; pb.y = *(uint32_t*)&b1;
            xa0[j * 32 + lane] = pa;
            xa1[j * 32 + lane] = pb;
        }
    }

    for (int o = 0; o < 33; o++) {
        const float* wrow = (o < 32) ? (w_wave + (size_t)o * CH) : w_exp;
        float d0 = 0.f, d1 = 0.f;
        #pragma unroll
        for (int j = 0; j < 8; j++) {
            const float4 w4 = *(const float4*)(wrow + j * 128 + lane * 4);
            d0 += xr0[j].x * w4.x + xr0[j].y * w4.y
                + xr0[j].z * w4.z + xr0[j].w * w4.w;
            d1 += xr1[j].x * w4.x + xr1[j].y * w4.y
                + xr1[j].z * w4.z + xr1[j].w * w4.w;
        }
        #pragma unroll
        for (int d = 16; d > 0; d >>= 1) {
            d0 += __shfl_xor_sync(0xffffffffu, d0, d);
            d1 += __shfl_xor_sync(0xffffffffu, d1, d);
        }
        if (lane == 0) {
            const float bv = (o < 32) ? b_wave[o] : b_exp[0];
            po[wid * 2][o]     = d0 + bv;
            po[wid * 2 + 1][o] = d1 + bv;
        }
    }
    __syncthreads();

    #pragma unroll
    for (int it = 0; it < 2; it++) {
        const int tk = wid + it * 8;
        const int gtok = blockIdx.x * 16 + tk;
        float v = po[tk][lane];
        float sq = v * v;
        #pragma unroll
        for (int d = 16; d > 0; d >>= 1) sq += __shfl_xor_sync(0xffffffffu, sq, d);
        const float r = rsqrtf(sq * (1.0f / 32.0f) + 1e-6f);
        const float sil = siluf(g_wave[lane] * v * r);
        if (lane < 16) {
            g_freq[(size_t)gtok * NHEAD + lane] = 15.0f / (1.0f + expf(-sil)) + 1.0f;
        } else {
            g_phase[(size_t)gtok * NHEAD + (lane - 16)] = tanhf(sil) * 16.0f;
        }
        if (lane == 0) {
            const float ve = po[tk][32];
            const float y = g_exp[0] * ve * rsqrtf(ve * ve + 1e-6f);
            g_expo[gtok] = (1.0f / (1.0f + expf(-y))) * 3.5f + 0.5f;
        }
    }
}

// ===========================================================================
// Stages 2 & 5: fp16 mma m16n8k16 GEMM, ldmatrix, BK=32, cp.async 4-stage.
// 128x128 CTA tile, 128 threads = 4 warps (2x2), warp tile = 64x64.
// 2 CTAs/SM. (r9 configuration — FROZEN)
// ===========================================================================
#define GSTRIDE 20                                     // u32 per row
#define STG 4
#define STAGE_U32 (128 * GSTRIDE)                      // 2560 u32 per matrix stage
#define GEMM_SMEM (STG * STAGE_U32 * 2 * 4)            // 81920 bytes

template <bool BIAS, bool SILU>
__global__ __launch_bounds__(128, 2) void gemm_tc_kernel(
    const __half* __restrict__ A, const __half* __restrict__ B,
    const float* __restrict__ bias, float* __restrict__ C)
{
    extern __shared__ uint32_t smem32[];
    const uint32_t smem_base = smem_u32(smem32);
    const uint32_t BOFF = STG * STAGE_U32 * 4;   // byte offset of B region

    const int tid  = threadIdx.x;
    const int wid  = tid >> 5;
    const int lane = tid & 31;
    const int gid  = lane >> 2;     // groupID 0..7
    const int tig  = lane & 3;      // thread-in-group 0..3
    const int wm   = wid & 1;       // warp row (0..1) -> 64 rows each
    const int wn   = wid >> 1;      // warp col (0..1) -> 64 cols each

    const int bm = blockIdx.y * 128;
    const int bn = blockIdx.x * 128;

    const int r0 = tid >> 2;        // 0..31
    const int cc = tid & 3;
    const uint32_t sbase = smem_base + (uint32_t)(r0 * GSTRIDE + cc * 4) * 4;
    const __half* gA0 = A + (size_t)(bm + r0) * CH + cc * 8;
    const __half* gB0 = B + (size_t)(bn + r0) * CH + cc * 8;

    const int rA = (lane & 7) + ((lane >> 3) & 1) * 8;
    const int kA = (lane >> 4) * 4;                      // u32
    uint32_t a_addr[4];
    #pragma unroll
    for (int mt = 0; mt < 4; mt++) {
        const int row = wm * 64 + mt * 16 + rA;
        a_addr[mt] = smem_base + (uint32_t)(row * GSTRIDE + kA) * 4;
    }
    const int rB = (lane & 7) + ((lane >> 4) << 3);
    const int kB = ((lane >> 3) & 1) * 4;                // u32
    uint32_t b_addr[4];
    #pragma unroll
    for (int pr = 0; pr < 4; pr++) {
        const int row = wn * 64 + pr * 16 + rB;
        b_addr[pr] = smem_base + BOFF + (uint32_t)(row * GSTRIDE + kB) * 4;
    }

    float c[4][8][4];
    #pragma unroll
    for (int mt = 0; mt < 4; mt++)
        #pragma unroll
        for (int nt = 0; nt < 8; nt++)
            #pragma unroll
            for (int j = 0; j < 4; j++) c[mt][nt][j] = 0.0f;

    const int NCHUNK = CH / 32;   // 32

    #pragma unroll
    for (int s = 0; s < STG - 1; s++) {
        const uint32_t so = (uint32_t)(s * STAGE_U32) * 4;
        #pragma unroll
        for (int i = 0; i < 4; i++) {
            const uint32_t ro = (uint32_t)(i * 32 * GSTRIDE) * 4;
            cp_async16(sbase + so + ro, gA0 + (size_t)(i * 32) * CH + s * 32);
            cp_async16(sbase + so + ro + BOFF, gB0 + (size_t)(i * 32) * CH + s * 32);
        }
        CP_COMMIT();
    }

    for (int kc = 0; kc < NCHUNK; kc++) {
        CP_WAIT2();
        __syncthreads();

        if (kc + STG - 1 < NCHUNK) {
            const uint32_t so = (uint32_t)(((kc + STG - 1) & (STG - 1)) * STAGE_U32) * 4;
            const int k0 = (kc + STG - 1) * 32;
            #pragma unroll
            for (int i = 0; i < 4; i++) {
                const uint32_t ro = (uint32_t)(i * 32 * GSTRIDE) * 4;
                cp_async16(sbase + so + ro, gA0 + (size_t)(i * 32) * CH + k0);
                cp_async16(sbase + so + ro + BOFF, gB0 + (size_t)(i * 32) * CH + k0);
            }
        }
        CP_COMMIT();

        const uint32_t soff = (uint32_t)((kc & (STG - 1)) * STAGE_U32) * 4;

        #pragma unroll
        for (int ksub = 0; ksub < 2; ksub++) {
            const uint32_t ko = soff + ksub * 32;   // 8 u32 = 32B per ksub
            uint32_t a[4][4], b[4][4];
            #pragma unroll
            for (int mt = 0; mt < 4; mt++) ldsm_x4(a[mt], a_addr[mt] + ko);
            #pragma unroll
            for (int pr = 0; pr < 4; pr++) ldsm_x4(b[pr], b_addr[pr] + ko);
            #pragma unroll
            for (int mt = 0; mt < 4; mt++) {
                #pragma unroll
                for (int nt = 0; nt < 8; nt++)
                    mma_f16_16x8x16(c[mt][nt], a[mt],
                                    b[nt >> 1][(nt & 1) * 2],
                                    b[nt >> 1][(nt & 1) * 2 + 1]);
            }
        }
    }

    #pragma unroll
    for (int mt = 0; mt < 4; mt++) {
        const int row = bm + wm * 64 + mt * 16 + gid;
        #pragma unroll
        for (int nt = 0; nt < 8; nt++) {
            const int col = bn + wn * 64 + nt * 8 + tig * 2;
            float u0 = c[mt][nt][0], u1 = c[mt][nt][1];
            float u2 = c[mt][nt][2], u3 = c[mt][nt][3];
            if (BIAS) {
                const float b0v = bias[col], b1v = bias[col + 1];
                u0 += b0v; u1 += b1v; u2 += b0v; u3 += b1v;
            }
            if (SILU) {
                u0 = siluf(u0); u1 = siluf(u1); u2 = siluf(u2); u3 = siluf(u3);
            }
            *(float2*)(C + (size_t)row * CH + col)       = make_float2(u0, u1);
            *(float2*)(C + (size_t)(row + 8) * CH + col) = make_float2(u2, u3);
        }
    }
}

// ===========================================================================
// rms_reduce: per-token rinv = rsqrt(mean(g_proj^2) + eps)
// ===========================================================================
__global__ __launch_bounds__(256) void rms_reduce_kernel()
{
    const int token = blockIdx.x;
    const int tid   = threadIdx.x;
    const int wid   = tid >> 5;
    const int lane  = tid & 31;
    __shared__ float red[8];

    const float4 v = ((const float4*)(g_proj + (size_t)token * CH))[tid];
    float sq = v.x * v.x + v.y * v.y + v.z * v.z + v.w * v.w;
    #pragma unroll
    for (int d = 16; d > 0; d >>= 1) sq += __shfl_xor_sync(0xffffffffu, sq, d);
    if (lane == 0) red[wid] = sq;
    __syncthreads();
    if (tid == 0) {
        float s = 0.f;
        #pragma unroll
        for (int i = 0; i < 8; i++) s += red[i];
        g_rinv[token] = rsqrtf(s * (1.0f / (float)CH) + 1e-6f);
    }
}

// ===========================================================================
// Stages 3+4: attention. Block = (16 consecutive tokens x ONE head),
// 512 threads = 16 warps, warp w -> token (tile*16 + w). Warp-local.
// Phase A packs per-sample scalars {kf, kc, flo} into ONE float4 ->
// phase B does 1 LDS.128 per iteration instead of 3 scalar LDS.
// Phase B: 2 samples/iter with 8B fp16 gathers.
// ===========================================================================
__global__ __launch_bounds__(512) void attn_kernel(
    const __half* __restrict__ xa, const float* __restrict__ gk)
{
    const int h    = blockIdx.x & (NHEAD - 1);
    const int tile = blockIdx.x >> 4;
    const int tid  = threadIdx.x;
    const int w    = tid >> 5;
    const int lane = tid & 31;

    const int gt = tile * 16 + w;          // this warp's token
    const int b  = gt >> 11;
    const int l  = gt & (SEQLEN - 1);

    __shared__ float  km[16][KSIZE];
    __shared__ float4 spk[16][34];         // {kf, kc, bitcast(flo), 0}

    // km for (token gt, head h): 64 channels, built warp-locally
    const float rinv = g_rinv[gt];
    {
        const float2 pj = ((const float2*)(g_proj + (size_t)gt * CH + h * HDIM))[lane];
        const float2 gg = ((const float2*)(gk + h * HDIM))[lane];
        km[w][lane * 2]     = siluf(gg.x * pj.x * rinv);
        km[w][lane * 2 + 1] = siluf(gg.y * pj.y * rinv);
    }
    __syncwarp();

    const float f = g_freq[(size_t)gt * NHEAD + h];
    const float p = g_phase[(size_t)gt * NHEAD + h];
    const float e = g_expo[gt];

    // Phase A: per-sample scalars (lane-parallel), slot 33 zero-padded
    for (int s = lane; s < 34; s += 32) {
        if (s >= 33) {
            spk[w][s] = make_float4(0.f, 0.f, __int_as_float(0), 0.f);
        } else {
            const float off = (float)(s - 16);
            const float rel = off * f;
            const float pos = (float)l + rel + p;
            const float validf = (pos >= 0.0f && pos < (float)SEQLEN) ? 1.0f : 0.0f;
            const float pc = fminf(fmaxf(pos, 0.0f), (float)SEQLEN - 1.001f);
            const int   fl = (int)floorf(pc);
            const float frac = pc - (float)fl;
            const float ar = fabsf(rel);
            const float powr = expf(-e * log1pf(ar * (1.0f / (float)SEQLEN)));
            const float idxf = fminf(ar * (1.0f / 256.0f), 1.0f) * 63.0f;
            int i0 = (int)idxf; if (i0 > 62) i0 = 62;
            const float wc = idxf - (float)i0;
            const float kern =
                (km[w][i0] * (1.0f - wc) + km[w][i0 + 1] * wc) * powr * validf;
            spk[w][s] = make_float4(kern * (1.0f - frac), kern * frac,
                                    __int_as_float(fl * (CH / 2)), 0.f);
        }
    }
    __syncwarp();

    // Phase B: 2 samples/iter. sh = parity, c4 = channel group (4 halves).
    const int sh = lane >> 4;
    const int c4 = lane & 15;
    const __half2* xb = (const __half2*)(xa + ((size_t)b * SEQLEN) * CH + h * HDIM);
    float a0 = 0.f, a1 = 0.f, a2 = 0.f, a3 = 0.f;
    #pragma unroll 17
    for (int sp = 0; sp < 17; sp++) {
        const float4 pk4 = spk[w][sp * 2 + sh];
        const float kf = pk4.x;
        const float kc = pk4.y;
        const int   o  = __float_as_int(pk4.z) + c4 * 2;
        const uint2 pf = *(const uint2*)(xb + o);
        const uint2 pcv = *(const uint2*)(xb + o + CH / 2);
        const float2 vf01 = __half22float2(*(const __half2*)&pf.x);
        const float2 vf23 = __half22float2(*(const __half2*)&pf.y);
        const float2 vc01 = __half22float2(*(const __half2*)&pcv.x);
        const float2 vc23 = __half22float2(*(const __half2*)&pcv.y);
        a0 += kf * vf01.x + kc * vc01.x;
        a1 += kf * vf01.y + kc * vc01.y;
        a2 += kf * vf23.x + kc * vc23.x;
        a3 += kf * vf23.y + kc * vc23.y;
    }
    // combine the two sample-parities
    a0 += __shfl_xor_sync(0xffffffffu, a0, 16);
    a1 += __shfl_xor_sync(0xffffffffu, a1, 16);
    a2 += __shfl_xor_sync(0xffffffffu, a2, 16);
    a3 += __shfl_xor_sync(0xffffffffu, a3, 16);

    if (lane < 16) {
        __half2 h0 = __floats2half2_rn(a0, a1);
        __half2 h1 = __floats2half2_rn(a2, a3);
        uint2 pk;
        pk.x = *(uint32_t*)&h0;
        pk.y = *(uint32_t*)&h1;
        ((uint2*)(g_ha + (size_t)gt * CH + h * HDIM))[c4] = pk;
    }
}

// ===========================================================================
// launch
// ===========================================================================
extern "C" void kernel_launch(void* const* d_in, const int* in_sizes, int n_in,
                              void* d_out, int out_size)
{
    const float* x      = (const float*)d_in[0];
    const float* w_wave = (const float*)d_in[1];
    const float* b_wave = (const float*)d_in[2];
    const float* g_wave = (const float*)d_in[3];
    const float* w_kern = (const float*)d_in[4];
    const float* b_kern = (const float*)d_in[5];
    const float* g_kern = (const float*)d_in[6];
    const float* w_exp  = (const float*)d_in[7];
    const float* b_exp  = (const float*)d_in[8];
    const float* g_exp  = (const float*)d_in[9];
    const float* w_out  = (const float*)d_in[10];
    float* out = (float*)d_out;

    float *proj_ptr;
    __half *xa_ptr, *ha_ptr, *wk_ptr, *wo_ptr;
    cudaGetSymbolAddress((void**)&proj_ptr, g_proj);
    cudaGetSymbolAddress((void**)&xa_ptr, g_xa);
    cudaGetSymbolAddress((void**)&ha_ptr, g_ha);
    cudaGetSymbolAddress((void**)&wk_ptr, g_wk);
    cudaGetSymbolAddress((void**)&wo_ptr, g_wo);

    cudaFuncSetAttribute(gemm_tc_kernel<true, false>,
                         cudaFuncAttributeMaxDynamicSharedMemorySize, GEMM_SMEM);
    cudaFuncSetAttribute(gemm_tc_kernel<false, true>,
                         cudaFuncAttributeMaxDynamicSharedMemorySize, GEMM_SMEM);

    // Stage 1: wave + exp projections (fp32) + x -> fp16
    proj_small_kernel<<<TOKENS / 16, 256>>>(x, w_wave, b_wave, g_wave,
                                            w_exp, b_exp, g_exp);

    // convert both weight matrices to fp16 (single launch)
    cvt_w_kernel<<<2 * (CH * CH / 4) / 256, 256>>>(w_kern, wk_ptr,
                                                   w_out, wo_ptr,
                                                   CH * CH / 4);

    // Stage 2: kern projection GEMM (+bias) via fp16 mma
    dim3 ggrid(CH / 128, TOKENS / 128);   // (8, 32) = 256 CTAs
    gemm_tc_kernel<true, false><<<ggrid, 128, GEMM_SMEM>>>(xa_ptr, wk_ptr,
                                                           b_kern, proj_ptr);

    // rms_reduce: per-token rinv
    rms_reduce_kernel<<<TOKENS, 256>>>();

    // Stages 3+4: attention (16 tokens x 1 head per block) -> hidden (fp16)
    attn_kernel<<<TOKENS / 16 * NHEAD, 512>>>(xa_ptr, g_kern);

    // Stage 5: output GEMM + silu via fp16 mma
    gemm_tc_kernel<false, true><<<ggrid, 128, GEMM_SMEM>>>(ha_ptr, wo_ptr,
                                                           nullptr, out);
}

// round 17
// speedup vs baseline: 1.0521x; 1.0225x over previous
#include <cuda_runtime.h>
#include <cuda_bf16.h>
#include <cuda_fp16.h>
#include <cstdint>
#include <math.h>

// ---------------------------------------------------------------------------
// TelephoneAttentionND  (B=2, L=2048, C=1024, H=16, D=64, K=64, S=33)
// Stage 1 (merged): proj (warp/2-tokens) -> freq/phase/expo + x fp16 (g_xa)
//                   AND w_kern/w_out -> fp16 (disjoint block ranges)
// Stage 2: kern GEMM [fp16 mma, r9 config] (+bias)               -> g_proj
// rms_reduce: per-token rinv                                     -> g_rinv
// Stage 3+4: attn (16 tokens x 1 head / block), fp16 gathers,
//            4 samples/iter with 16B loads                       -> g_ha
// Stage 5: out GEMM + silu                                       -> d_out
// ---------------------------------------------------------------------------

#define BATCH 2
#define SEQLEN 2048
#define CH 1024
#define NHEAD 16
#define HDIM 64
#define KSIZE 64
#define TOKENS (BATCH * SEQLEN)   // 4096

#define CVT_BLOCKS (2 * (CH * CH / 4) / 256)   // 2048
#define PROJ_BLOCKS (TOKENS / 16)              // 256

// scratch (device globals; no allocation allowed)
__device__ float g_freq[TOKENS * NHEAD];
__device__ float g_phase[TOKENS * NHEAD];
__device__ float g_expo[TOKENS];
__device__ float g_rinv[TOKENS];
__device__ float g_proj[(size_t)TOKENS * CH];   // gemm1 out (fp32)
__device__ __half g_xa[(size_t)TOKENS * CH];    // x in fp16
__device__ __half g_ha[(size_t)TOKENS * CH];    // hidden in fp16
__device__ __half g_wk[(size_t)CH * CH];        // w_kern fp16
__device__ __half g_wo[(size_t)CH * CH];        // w_out fp16

__device__ __forceinline__ float siluf(float v) {
    return v / (1.0f + expf(-v));
}

__device__ __forceinline__ void mma_f16_16x8x16(
    float c[4], const uint32_t a[4], uint32_t b0, uint32_t b1)
{
    asm volatile(
        "mma.sync.aligned.m16n8k16.row.col.f32.f16.f16.f32 "
        "{%0, %1, %2, %3}, {%4, %5, %6, %7}, {%8, %9}, {%0, %1, %2, %3};"
        : "+f"(c[0]), "+f"(c[1]), "+f"(c[2]), "+f"(c[3])
        : "r"(a[0]), "r"(a[1]), "r"(a[2]), "r"(a[3]), "r"(b0), "r"(b1));
}

__device__ __forceinline__ void ldsm_x4(uint32_t r[4], uint32_t addr) {
    asm volatile(
        "ldmatrix.sync.aligned.m8n8.x4.shared.b16 {%0, %1, %2, %3}, [%4];"
        : "=r"(r[0]), "=r"(r[1]), "=r"(r[2]), "=r"(r[3]) : "r"(addr));
}

__device__ __forceinline__ uint32_t smem_u32(const void* p) {
    uint32_t a;
    asm("{ .reg .u64 t; cvta.to.shared.u64 t, %1; cvt.u32.u64 %0, t; }"
        : "=r"(a) : "l"(p));
    return a;
}

__device__ __forceinline__ void cp_async16(uint32_t dst, const void* src) {
    asm volatile("cp.async.ca.shared.global [%0], [%1], 16;"
                 :: "r"(dst), "l"(src));
}
#define CP_COMMIT() asm volatile("cp.async.commit_group;" ::: "memory")
#define CP_WAIT2()  asm volatile("cp.async.wait_group 2;" ::: "memory")

// ===========================================================================
// Stage 1 (merged): blocks [0, CVT_BLOCKS) convert weights to fp16;
// blocks [CVT_BLOCKS, CVT_BLOCKS+PROJ_BLOCKS) run the wave/exp projection.
// ===========================================================================
__global__ __launch_bounds__(256) void proj_cvt_kernel(
    const float* __restrict__ x,
    const float* __restrict__ w_wave, const float* __restrict__ b_wave,
    const float* __restrict__ g_wave,
    const float* __restrict__ w_exp, const float* __restrict__ b_exp,
    const float* __restrict__ g_exp,
    const float* __restrict__ wk_in, const float* __restrict__ wo_in)
{
    const int tid = threadIdx.x;

    if (blockIdx.x < CVT_BLOCKS) {
        // weight conversion part
        const int n4each = CH * CH / 4;
        int idx = blockIdx.x * 256 + tid;
        const float* in;
        __half* out;
        if (idx < n4each) {
            in = wk_in; out = g_wk;
        } else {
            in = wo_in; out = g_wo; idx -= n4each;
        }
        const float4 v = ((const float4*)in)[idx];
        __half2 h0 = __floats2half2_rn(v.x, v.y);
        __half2 h1 = __floats2half2_rn(v.z, v.w);
        uint2 o;
        o.x = *(uint32_t*)&h0;
        o.y = *(uint32_t*)&h1;
        ((uint2*)out)[idx] = o;
        return;
    }

    const int pbid = blockIdx.x - CVT_BLOCKS;
    const int wid  = tid >> 5;
    const int lane = tid & 31;
    const int tok0 = pbid * 16 + wid * 2;

    __shared__ float po[16][34];

    float4 xr0[8], xr1[8];
    {
        const float* x0 = x + (size_t)tok0 * CH;
        const float* x1 = x0 + CH;
        uint2* xa0 = (uint2*)(g_xa + (size_t)tok0 * CH);
        uint2* xa1 = (uint2*)(g_xa + (size_t)(tok0 + 1) * CH);
        #pragma unroll
        for (int j = 0; j < 8; j++) {
            xr0[j] = *(const float4*)(x0 + j * 128 + lane * 4);
            xr1[j] = *(const float4*)(x1 + j * 128 + lane * 4);
            __half2 a0 = __floats2half2_rn(xr0[j].x, xr0[j].y);
            __half2 a1 = __floats2half2_rn(xr0[j].z, xr0[j].w);
            __half2 b0 = __floats2half2_rn(xr1[j].x, xr1[j].y);
            __half2 b1 = __floats2half2_rn(xr1[j].z, xr1[j].w);
            uint2 pa, pb;
            pa.x = *(uint32_t*)&a0; pa.y = *(uint32_t*)&a1;
            pb.x = *(uint32_t*)&b0; pb.y = *(uint32_t*)&b1;
            xa0[j * 32 + lane] = pa;
            xa1[j * 32 + lane] = pb;
        }
    }

    for (int o = 0; o < 33; o++) {
        const float* wrow = (o < 32) ? (w_wave + (size_t)o * CH) : w_exp;
        float d0 = 0.f, d1 = 0.f;
        #pragma unroll
        for (int j = 0; j < 8; j++) {
            const float4 w4 = *(const float4*)(wrow + j * 128 + lane * 4);
            d0 += xr0[j].x * w4.x + xr0[j].y * w4.y
                + xr0[j].z * w4.z + xr0[j].w * w4.w;
            d1 += xr1[j].x * w4.x + xr1[j].y * w4.y
                + xr1[j].z * w4.z + xr1[j].w * w4.w;
        }
        #pragma unroll
        for (int d = 16; d > 0; d >>= 1) {
            d0 += __shfl_xor_sync(0xffffffffu, d0, d);
            d1 += __shfl_xor_sync(0xffffffffu, d1, d);
        }
        if (lane == 0) {
            const float bv = (o < 32) ? b_wave[o] : b_exp[0];
            po[wid * 2][o]     = d0 + bv;
            po[wid * 2 + 1][o] = d1 + bv;
        }
    }
    __syncthreads();

    #pragma unroll
    for (int it = 0; it < 2; it++) {
        const int tk = wid + it * 8;
        const int gtok = pbid * 16 + tk;
        float v = po[tk][lane];
        float sq = v * v;
        #pragma unroll
        for (int d = 16; d > 0; d >>= 1) sq += __shfl_xor_sync(0xffffffffu, sq, d);
        const float r = rsqrtf(sq * (1.0f / 32.0f) + 1e-6f);
        const float sil = siluf(g_wave[lane] * v * r);
        if (lane < 16) {
            g_freq[(size_t)gtok * NHEAD + lane] = 15.0f / (1.0f + expf(-sil)) + 1.0f;
        } else {
            g_phase[(size_t)gtok * NHEAD + (lane - 16)] = tanhf(sil) * 16.0f;
        }
        if (lane == 0) {
            const float ve = po[tk][32];
            const float y = g_exp[0] * ve * rsqrtf(ve * ve + 1e-6f);
            g_expo[gtok] = (1.0f / (1.0f + expf(-y))) * 3.5f + 0.5f;
        }
    }
}

// ===========================================================================
// Stages 2 & 5: fp16 mma m16n8k16 GEMM, ldmatrix, BK=32, cp.async 4-stage.
// 128x128 CTA tile, 128 threads = 4 warps (2x2), warp tile = 64x64.
// 2 CTAs/SM. (r9 configuration — FROZEN)
// ===========================================================================
#define GSTRIDE 20                                     // u32 per row
#define STG 4
#define STAGE_U32 (128 * GSTRIDE)                      // 2560 u32 per matrix stage
#define GEMM_SMEM (STG * STAGE_U32 * 2 * 4)            // 81920 bytes

template <bool BIAS, bool SILU>
__global__ __launch_bounds__(128, 2) void gemm_tc_kernel(
    const __half* __restrict__ A, const __half* __restrict__ B,
    const float* __restrict__ bias, float* __restrict__ C)
{
    extern __shared__ uint32_t smem32[];
    const uint32_t smem_base = smem_u32(smem32);
    const uint32_t BOFF = STG * STAGE_U32 * 4;   // byte offset of B region

    const int tid  = threadIdx.x;
    const int wid  = tid >> 5;
    const int lane = tid & 31;
    const int gid  = lane >> 2;     // groupID 0..7
    const int tig  = lane & 3;      // thread-in-group 0..3
    const int wm   = wid & 1;       // warp row (0..1) -> 64 rows each
    const int wn   = wid >> 1;      // warp col (0..1) -> 64 cols each

    const int bm = blockIdx.y * 128;
    const int bn = blockIdx.x * 128;

    const int r0 = tid >> 2;        // 0..31
    const int cc = tid & 3;
    const uint32_t sbase = smem_base + (uint32_t)(r0 * GSTRIDE + cc * 4) * 4;
    const __half* gA0 = A + (size_t)(bm + r0) * CH + cc * 8;
    const __half* gB0 = B + (size_t)(bn + r0) * CH + cc * 8;

    const int rA = (lane & 7) + ((lane >> 3) & 1) * 8;
    const int kA = (lane >> 4) * 4;                      // u32
    uint32_t a_addr[4];
    #pragma unroll
    for (int mt = 0; mt < 4; mt++) {
        const int row = wm * 64 + mt * 16 + rA;
        a_addr[mt] = smem_base + (uint32_t)(row * GSTRIDE + kA) * 4;
    }
    const int rB = (lane & 7) + ((lane >> 4) << 3);
    const int kB = ((lane >> 3) & 1) * 4;                // u32
    uint32_t b_addr[4];
    #pragma unroll
    for (int pr = 0; pr < 4; pr++) {
        const int row = wn * 64 + pr * 16 + rB;
        b_addr[pr] = smem_base + BOFF + (uint32_t)(row * GSTRIDE + kB) * 4;
    }

    float c[4][8][4];
    #pragma unroll
    for (int mt = 0; mt < 4; mt++)
        #pragma unroll
        for (int nt = 0; nt < 8; nt++)
            #pragma unroll
            for (int j = 0; j < 4; j++) c[mt][nt][j] = 0.0f;

    const int NCHUNK = CH / 32;   // 32

    #pragma unroll
    for (int s = 0; s < STG - 1; s++) {
        const uint32_t so = (uint32_t)(s * STAGE_U32) * 4;
        #pragma unroll
        for (int i = 0; i < 4; i++) {
            const uint32_t ro = (uint32_t)(i * 32 * GSTRIDE) * 4;
            cp_async16(sbase + so + ro, gA0 + (size_t)(i * 32) * CH + s * 32);
            cp_async16(sbase + so + ro + BOFF, gB0 + (size_t)(i * 32) * CH + s * 32);
        }
        CP_COMMIT();
    }

    for (int kc = 0; kc < NCHUNK; kc++) {
        CP_WAIT2();
        __syncthreads();

        if (kc + STG - 1 < NCHUNK) {
            const uint32_t so = (uint32_t)(((kc + STG - 1) & (STG - 1)) * STAGE_U32) * 4;
            const int k0 = (kc + STG - 1) * 32;
            #pragma unroll
            for (int i = 0; i < 4; i++) {
                const uint32_t ro = (uint32_t)(i * 32 * GSTRIDE) * 4;
                cp_async16(sbase + so + ro, gA0 + (size_t)(i * 32) * CH + k0);
                cp_async16(sbase + so + ro + BOFF, gB0 + (size_t)(i * 32) * CH + k0);
            }
        }
        CP_COMMIT();

        const uint32_t soff = (uint32_t)((kc & (STG - 1)) * STAGE_U32) * 4;

        #pragma unroll
        for (int ksub = 0; ksub < 2; ksub++) {
            const uint32_t ko = soff + ksub * 32;   // 8 u32 = 32B per ksub
            uint32_t a[4][4], b[4][4];
            #pragma unroll
            for (int mt = 0; mt < 4; mt++) ldsm_x4(a[mt], a_addr[mt] + ko);
            #pragma unroll
            for (int pr = 0; pr < 4; pr++) ldsm_x4(b[pr], b_addr[pr] + ko);
            #pragma unroll
            for (int mt = 0; mt < 4; mt++) {
                #pragma unroll
                for (int nt = 0; nt < 8; nt++)
                    mma_f16_16x8x16(c[mt][nt], a[mt],
                                    b[nt >> 1][(nt & 1) * 2],
                                    b[nt >> 1][(nt & 1) * 2 + 1]);
            }
        }
    }

    #pragma unroll
    for (int mt = 0; mt < 4; mt++) {
        const int row = bm + wm * 64 + mt * 16 + gid;
        #pragma unroll
        for (int nt = 0; nt < 8; nt++) {
            const int col = bn + wn * 64 + nt * 8 + tig * 2;
            float u0 = c[mt][nt][0], u1 = c[mt][nt][1];
            float u2 = c[mt][nt][2], u3 = c[mt][nt][3];
            if (BIAS) {
                const float b0v = bias[col], b1v = bias[col + 1];
                u0 += b0v; u1 += b1v; u2 += b0v; u3 += b1v;
            }
            if (SILU) {
                u0 = siluf(u0); u1 = siluf(u1); u2 = siluf(u2); u3 = siluf(u3);
            }
            *(float2*)(C + (size_t)row * CH + col)       = make_float2(u0, u1);
            *(float2*)(C + (size_t)(row + 8) * CH + col) = make_float2(u2, u3);
        }
    }
}

// ===========================================================================
// rms_reduce: per-token rinv = rsqrt(mean(g_proj^2) + eps)
// ===========================================================================
__global__ __launch_bounds__(256) void rms_reduce_kernel()
{
    const int token = blockIdx.x;
    const int tid   = threadIdx.x;
    const int wid   = tid >> 5;
    const int lane  = tid & 31;
    __shared__ float red[8];

    const float4 v = ((const float4*)(g_proj + (size_t)token * CH))[tid];
    float sq = v.x * v.x + v.y * v.y + v.z * v.z + v.w * v.w;
    #pragma unroll
    for (int d = 16; d > 0; d >>= 1) sq += __shfl_xor_sync(0xffffffffu, sq, d);
    if (lane == 0) red[wid] = sq;
    __syncthreads();
    if (tid == 0) {
        float s = 0.f;
        #pragma unroll
        for (int i = 0; i < 8; i++) s += red[i];
        g_rinv[token] = rsqrtf(s * (1.0f / (float)CH) + 1e-6f);
    }
}

// ===========================================================================
// Stages 3+4: attention. Block = (16 consecutive tokens x ONE head),
// 512 threads = 16 warps, warp w -> token (tile*16 + w). Warp-local.
// Phase B: 4 samples/iter. lane>>3 = sample sub-parity (0..3),
// lane&7 = 8-channel group -> one 16B fp16 gather pair per iter.
// 9 iterations cover 36 sample slots (33 real + 3 zero-padded).
// ===========================================================================
__global__ __launch_bounds__(512) void attn_kernel(
    const __half* __restrict__ xa, const float* __restrict__ gk)
{
    const int h    = blockIdx.x & (NHEAD - 1);
    const int tile = blockIdx.x >> 4;
    const int tid  = threadIdx.x;
    const int w    = tid >> 5;
    const int lane = tid & 31;

    const int gt = tile * 16 + w;          // this warp's token
    const int b  = gt >> 11;
    const int l  = gt & (SEQLEN - 1);

    __shared__ float  km[16][KSIZE];
    __shared__ float4 spk[16][36];         // {kf, kc, bitcast(flo), 0}

    // km for (token gt, head h): 64 channels, built warp-locally
    const float rinv = g_rinv[gt];
    {
        const float2 pj = ((const float2*)(g_proj + (size_t)gt * CH + h * HDIM))[lane];
        const float2 gg = ((const float2*)(gk + h * HDIM))[lane];
        km[w][lane * 2]     = siluf(gg.x * pj.x * rinv);
        km[w][lane * 2 + 1] = siluf(gg.y * pj.y * rinv);
    }
    __syncwarp();

    const float f = g_freq[(size_t)gt * NHEAD + h];
    const float p = g_phase[(size_t)gt * NHEAD + h];
    const float e = g_expo[gt];

    // Phase A: per-sample scalars (lane-parallel), slots 33..35 zero-padded
    for (int s = lane; s < 36; s += 32) {
        if (s >= 33) {
            spk[w][s] = make_float4(0.f, 0.f, __int_as_float(0), 0.f);
        } else {
            const float off = (float)(s - 16);
            const float rel = off * f;
            const float pos = (float)l + rel + p;
            const float validf = (pos >= 0.0f && pos < (float)SEQLEN) ? 1.0f : 0.0f;
            const float pc = fminf(fmaxf(pos, 0.0f), (float)SEQLEN - 1.001f);
            const int   fl = (int)floorf(pc);
            const float frac = pc - (float)fl;
            const float ar = fabsf(rel);
            const float powr = expf(-e * log1pf(ar * (1.0f / (float)SEQLEN)));
            const float idxf = fminf(ar * (1.0f / 256.0f), 1.0f) * 63.0f;
            int i0 = (int)idxf; if (i0 > 62) i0 = 62;
            const float wc = idxf - (float)i0;
            const float kern =
                (km[w][i0] * (1.0f - wc) + km[w][i0 + 1] * wc) * powr * validf;
            spk[w][s] = make_float4(kern * (1.0f - frac), kern * frac,
                                    __int_as_float(fl * (CH / 2)), 0.f);
        }
    }
    __syncwarp();

    // Phase B: 4 samples/iter, 16B fp16 gathers.
    const int sh = lane >> 3;              // sample sub-parity 0..3
    const int c8 = lane & 7;               // 8-channel group
    const __half2* xb = (const __half2*)(xa + ((size_t)b * SEQLEN) * CH + h * HDIM);
    float a0 = 0.f, a1 = 0.f, a2 = 0.f, a3 = 0.f;
    float a4 = 0.f, a5 = 0.f, a6 = 0.f, a7 = 0.f;
    #pragma unroll 9
    for (int sp = 0; sp < 9; sp++) {
        const float4 pk4 = spk[w][sp * 4 + sh];
        const float kf = pk4.x;
        const float kc = pk4.y;
        const int   o  = __float_as_int(pk4.z) + c8 * 4;
        const uint4 pf  = *(const uint4*)(xb + o);
        const uint4 pcv = *(const uint4*)(xb + o + CH / 2);
        const float2 f0 = __half22float2(*(const __half2*)&pf.x);
        const float2 f1 = __half22float2(*(const __half2*)&pf.y);
        const float2 f2 = __half22float2(*(const __half2*)&pf.z);
        const float2 f3 = __half22float2(*(const __half2*)&pf.w);
        const float2 c0 = __half22float2(*(const __half2*)&pcv.x);
        const float2 c1 = __half22float2(*(const __half2*)&pcv.y);
        const float2 c2 = __half22float2(*(const __half2*)&pcv.z);
        const float2 c3 = __half22float2(*(const __half2*)&pcv.w);
        a0 += kf * f0.x + kc * c0.x;
        a1 += kf * f0.y + kc * c0.y;
        a2 += kf * f1.x + kc * c1.x;
        a3 += kf * f1.y + kc * c1.y;
        a4 += kf * f2.x + kc * c2.x;
        a5 += kf * f2.y + kc * c2.y;
        a6 += kf * f3.x + kc * c3.x;
        a7 += kf * f3.y + kc * c3.y;
    }
    // combine the four sample sub-parities
    #pragma unroll
    for (int d = 8; d <= 16; d <<= 1) {
        a0 += __shfl_xor_sync(0xffffffffu, a0, d);
        a1 += __shfl_xor_sync(0xffffffffu, a1, d);
        a2 += __shfl_xor_sync(0xffffffffu, a2, d);
        a3 += __shfl_xor_sync(0xffffffffu, a3, d);
        a4 += __shfl_xor_sync(0xffffffffu, a4, d);
        a5 += __shfl_xor_sync(0xffffffffu, a5, d);
        a6 += __shfl_xor_sync(0xffffffffu, a6, d);
        a7 += __shfl_xor_sync(0xffffffffu, a7, d);
    }

    if (lane < 8) {
        __half2 h0 = __floats2half2_rn(a0, a1);
        __half2 h1 = __floats2half2_rn(a2, a3);
        __half2 h2 = __floats2half2_rn(a4, a5);
        __half2 h3 = __floats2half2_rn(a6, a7);
        uint4 pk;
        pk.x = *(uint32_t*)&h0;
        pk.y = *(uint32_t*)&h1;
        pk.z = *(uint32_t*)&h2;
        pk.w = *(uint32_t*)&h3;
        ((uint4*)(g_ha + (size_t)gt * CH + h * HDIM))[c8] = pk;
    }
}

// ===========================================================================
// launch
// ===========================================================================
extern "C" void kernel_launch(void* const* d_in, const int* in_sizes, int n_in,
                              void* d_out, int out_size)
{
    const float* x      = (const float*)d_in[0];
    const float* w_wave = (const float*)d_in[1];
    const float* b_wave = (const float*)d_in[2];
    const float* g_wave = (const float*)d_in[3];
    const float* w_kern = (const float*)d_in[4];
    const float* b_kern = (const float*)d_in[5];
    const float* g_kern = (const float*)d_in[6];
    const float* w_exp  = (const float*)d_in[7];
    const float* b_exp  = (const float*)d_in[8];
    const float* g_exp  = (const float*)d_in[9];
    const float* w_out  = (const float*)d_in[10];
    float* out = (float*)d_out;

    float *proj_ptr;
    __half *xa_ptr, *ha_ptr, *wk_ptr, *wo_ptr;
    cudaGetSymbolAddress((void**)&proj_ptr, g_proj);
    cudaGetSymbolAddress((void**)&xa_ptr, g_xa);
    cudaGetSymbolAddress((void**)&ha_ptr, g_ha);
    cudaGetSymbolAddress((void**)&wk_ptr, g_wk);
    cudaGetSymbolAddress((void**)&wo_ptr, g_wo);

    cudaFuncSetAttribute(gemm_tc_kernel<true, false>,
                         cudaFuncAttributeMaxDynamicSharedMemorySize, GEMM_SMEM);
    cudaFuncSetAttribute(gemm_tc_kernel<false, true>,
                         cudaFuncAttributeMaxDynamicSharedMemorySize, GEMM_SMEM);

    // Stage 1 (merged): weight cvt + wave/exp projections + x -> fp16
    proj_cvt_kernel<<<CVT_BLOCKS + PROJ_BLOCKS, 256>>>(
        x, w_wave, b_wave, g_wave, w_exp, b_exp, g_exp, w_kern, w_out);

    // Stage 2: kern projection GEMM (+bias) via fp16 mma
    dim3 ggrid(CH / 128, TOKENS / 128);   // (8, 32) = 256 CTAs
    gemm_tc_kernel<true, false><<<ggrid, 128, GEMM_SMEM>>>(xa_ptr, wk_ptr,
                                                           b_kern, proj_ptr);

    // rms_reduce: per-token rinv
    rms_reduce_kernel<<<TOKENS, 256>>>();

    // Stages 3+4: attention (16 tokens x 1 head per block) -> hidden (fp16)
    attn_kernel<<<TOKENS / 16 * NHEAD, 512>>>(xa_ptr, g_kern);

    // Stage 5: output GEMM + silu via fp16 mma
    gemm_tc_kernel<false, true><<<ggrid, 128, GEMM_SMEM>>>(ha_ptr, wo_ptr,
                                                           nullptr, out);
}